// round 1
// baseline (speedup 1.0000x reference)
#include <cuda_runtime.h>
#include <cuda_bf16.h>
#include <cstdint>

#define BB 4
#define TT 2048
#define CC 1024
#define HH 16
#define DD 64
#define NTOK (BB*TT)   // 8192

// Scratch (device globals; no allocation)
__device__ float g_q[(size_t)BB*HH*TT*DD];
__device__ float g_k[(size_t)BB*HH*TT*DD];
__device__ float g_v[(size_t)BB*HH*TT*DD];
__device__ float g_y[(size_t)NTOK*CC];

// ---------------------------------------------------------------------------
// Linear: out[n][o] = sum_c A[n][c] * W[o][c] + bias[o]
// Tile: BM=64 (n) x BN=128 (o), BK=16. 256 threads, 4x8 micro-tile.
// src_sel: 0 -> A_ext, 1 -> g_y
// dst_sel: 0/1/2 -> g_q/g_k/g_v in [B,H,T,D] layout; 3 -> out_ext row-major
// ---------------------------------------------------------------------------
__global__ __launch_bounds__(256) void linear_kernel(
    const float* __restrict__ A_ext, const float* __restrict__ W,
    const float* __restrict__ bias, float* __restrict__ out_ext,
    int src_sel, int dst_sel)
{
    __shared__ float As[16][68];
    __shared__ float Bs[16][132];

    const float* __restrict__ A = (src_sel == 0) ? A_ext : g_y;

    const int tid = threadIdx.x;
    const int tx = tid & 15;
    const int ty = tid >> 4;
    const int n0 = blockIdx.x * 64;
    const int o0 = blockIdx.y * 128;

    float acc[4][8];
#pragma unroll
    for (int i = 0; i < 4; i++)
#pragma unroll
        for (int j = 0; j < 8; j++) acc[i][j] = 0.f;

    const int ldn = tid >> 2;          // 0..63
    const int ldk = (tid & 3) * 4;     // 0,4,8,12

    for (int k0 = 0; k0 < CC; k0 += 16) {
        // A tile: 64 x 16
        {
            float4 v = *(const float4*)(A + (size_t)(n0 + ldn) * CC + k0 + ldk);
            As[ldk + 0][ldn] = v.x; As[ldk + 1][ldn] = v.y;
            As[ldk + 2][ldn] = v.z; As[ldk + 3][ldn] = v.w;
        }
        // W tile: 128 x 16
#pragma unroll
        for (int r = 0; r < 2; r++) {
            int oo = ldn + r * 64;
            float4 v = *(const float4*)(W + (size_t)(o0 + oo) * CC + k0 + ldk);
            Bs[ldk + 0][oo] = v.x; Bs[ldk + 1][oo] = v.y;
            Bs[ldk + 2][oo] = v.z; Bs[ldk + 3][oo] = v.w;
        }
        __syncthreads();

#pragma unroll
        for (int kk = 0; kk < 16; kk++) {
            float4 a = *(const float4*)&As[kk][ty * 4];
            float4 b0 = *(const float4*)&Bs[kk][tx * 4];
            float4 b1 = *(const float4*)&Bs[kk][64 + tx * 4];
            float av[4] = {a.x, a.y, a.z, a.w};
            float bv[8] = {b0.x, b0.y, b0.z, b0.w, b1.x, b1.y, b1.z, b1.w};
#pragma unroll
            for (int i = 0; i < 4; i++)
#pragma unroll
                for (int j = 0; j < 8; j++)
                    acc[i][j] += av[i] * bv[j];
        }
        __syncthreads();
    }

    // epilogue
    float* __restrict__ qkv = (dst_sel == 0) ? g_q : (dst_sel == 1) ? g_k : g_v;
#pragma unroll
    for (int i = 0; i < 4; i++) {
        int n = n0 + ty * 4 + i;
#pragma unroll
        for (int j = 0; j < 8; j++) {
            int o = o0 + ((j < 4) ? (tx * 4 + j) : (64 + tx * 4 + j - 4));
            float val = acc[i][j] + bias[o];
            if (dst_sel == 3) {
                out_ext[(size_t)n * CC + o] = val;
            } else {
                int b = n >> 11, t = n & (TT - 1);
                int h = o >> 6, dd = o & 63;
                qkv[(((size_t)(b * HH + h) * TT + t) << 6) + dd] = val;
            }
        }
    }
}

// ---------------------------------------------------------------------------
// Flash attention, fp32, causal. One CTA = one (b,h) x 64-query tile.
// grid: (T/64 = 32, B*H = 64), block 256 (16x16 threads, 4x4 micro-tile).
// Dynamic smem: Qs,Ks,Ps [d/k][q] stride 68 ; Vs [k][d] stride 68.
// ---------------------------------------------------------------------------
__global__ __launch_bounds__(256) void attn_kernel()
{
    extern __shared__ float smem[];
    float* Qs = smem;                  // [64][68] (d-major: Qs[d*68+q])
    float* Ks = Qs + 64 * 68;          // [64][68] (d-major)
    float* Vs = Ks + 64 * 68;          // [64][68] (k-major: Vs[k*68+d])
    float* Ps = Vs + 64 * 68;          // [64][68] (k-major: Ps[k*68+q])

    const int tid = threadIdx.x;
    const int tx = tid & 15;
    const int ty = tid >> 4;
    const int qi = blockIdx.x;
    const int bh = blockIdx.y;
    const int q0 = qi * 64;

    const float* __restrict__ Qp = g_q + (size_t)bh * TT * DD;
    const float* __restrict__ Kp = g_k + (size_t)bh * TT * DD;
    const float* __restrict__ Vp = g_v + (size_t)bh * TT * DD;

    const int ldn = tid >> 2;
    const int ldk0 = (tid & 3) * 4;

    // load Q tile transposed: Qs[d][q]
#pragma unroll
    for (int cg = 0; cg < 4; cg++) {
        int kk = ldk0 + cg * 16;
        float4 v = *(const float4*)(Qp + (size_t)(q0 + ldn) * DD + kk);
        Qs[(kk + 0) * 68 + ldn] = v.x; Qs[(kk + 1) * 68 + ldn] = v.y;
        Qs[(kk + 2) * 68 + ldn] = v.z; Qs[(kk + 3) * 68 + ldn] = v.w;
    }

    float m_i[4], l_i[4], acc[4][4];
#pragma unroll
    for (int i = 0; i < 4; i++) {
        m_i[i] = -3.4e38f; l_i[i] = 0.f;
#pragma unroll
        for (int j = 0; j < 4; j++) acc[i][j] = 0.f;
    }

    for (int kt = 0; kt <= qi; kt++) {
        const int k0 = kt * 64;
        __syncthreads();   // prior iteration's smem reads done (also covers Q load)

        // load K (transposed) and V (straight)
#pragma unroll
        for (int cg = 0; cg < 4; cg++) {
            int kk = ldk0 + cg * 16;
            float4 kv = *(const float4*)(Kp + (size_t)(k0 + ldn) * DD + kk);
            Ks[(kk + 0) * 68 + ldn] = kv.x; Ks[(kk + 1) * 68 + ldn] = kv.y;
            Ks[(kk + 2) * 68 + ldn] = kv.z; Ks[(kk + 3) * 68 + ldn] = kv.w;
            float4 vv = *(const float4*)(Vp + (size_t)(k0 + ldn) * DD + kk);
            *(float4*)&Vs[ldn * 68 + kk] = vv;
        }
        __syncthreads();

        // S = Q K^T (this thread: rows ty*4..+3, cols tx*4..+3)
        float s[4][4];
#pragma unroll
        for (int i = 0; i < 4; i++)
#pragma unroll
            for (int j = 0; j < 4; j++) s[i][j] = 0.f;

#pragma unroll 8
        for (int kk = 0; kk < 64; kk++) {
            float4 a = *(const float4*)&Qs[kk * 68 + ty * 4];
            float4 b = *(const float4*)&Ks[kk * 68 + tx * 4];
            float av[4] = {a.x, a.y, a.z, a.w};
            float bv[4] = {b.x, b.y, b.z, b.w};
#pragma unroll
            for (int i = 0; i < 4; i++)
#pragma unroll
                for (int j = 0; j < 4; j++)
                    s[i][j] += av[i] * bv[j];
        }

        const bool diag = (kt == qi);
#pragma unroll
        for (int i = 0; i < 4; i++)
#pragma unroll
            for (int j = 0; j < 4; j++) {
                s[i][j] *= 0.125f;  // 1/sqrt(64)
                if (diag && (tx * 4 + j > ty * 4 + i)) s[i][j] = -3.0e38f;
            }

        // online softmax per row
#pragma unroll
        for (int i = 0; i < 4; i++) {
            float mx = fmaxf(fmaxf(s[i][0], s[i][1]), fmaxf(s[i][2], s[i][3]));
#pragma unroll
            for (int off = 8; off > 0; off >>= 1)
                mx = fmaxf(mx, __shfl_xor_sync(0xffffffffu, mx, off));
            float mnew = fmaxf(m_i[i], mx);
            float fac = __expf(m_i[i] - mnew);   // -3.4e38 - finite -> 0
            float rs = 0.f;
#pragma unroll
            for (int j = 0; j < 4; j++) {
                float p = __expf(s[i][j] - mnew);
                s[i][j] = p;
                rs += p;
            }
#pragma unroll
            for (int off = 8; off > 0; off >>= 1)
                rs += __shfl_xor_sync(0xffffffffu, rs, off);
            l_i[i] = l_i[i] * fac + rs;
            m_i[i] = mnew;
#pragma unroll
            for (int j = 0; j < 4; j++) acc[i][j] *= fac;
        }

        // P to smem transposed: Ps[k][q]
#pragma unroll
        for (int i = 0; i < 4; i++)
#pragma unroll
            for (int j = 0; j < 4; j++)
                Ps[(tx * 4 + j) * 68 + ty * 4 + i] = s[i][j];
        __syncthreads();

        // acc += P V   (this thread: rows q=ty*4..+3, cols d=tx*4..+3)
#pragma unroll 8
        for (int kk = 0; kk < 64; kk++) {
            float4 a = *(const float4*)&Ps[kk * 68 + ty * 4];
            float4 b = *(const float4*)&Vs[kk * 68 + tx * 4];
            float av[4] = {a.x, a.y, a.z, a.w};
            float bv[4] = {b.x, b.y, b.z, b.w};
#pragma unroll
            for (int i = 0; i < 4; i++)
#pragma unroll
                for (int j = 0; j < 4; j++)
                    acc[i][j] += av[i] * bv[j];
        }
    }

    // write y[b][t][h*64+d]
    const int b = bh >> 4, h = bh & 15;
#pragma unroll
    for (int i = 0; i < 4; i++) {
        int tq = q0 + ty * 4 + i;
        float inv = 1.f / l_i[i];
#pragma unroll
        for (int j = 0; j < 4; j++)
            g_y[(size_t)(b * TT + tq) * CC + h * 64 + tx * 4 + j] = acc[i][j] * inv;
    }
}

// ---------------------------------------------------------------------------
extern "C" void kernel_launch(void* const* d_in, const int* in_sizes, int n_in,
                              void* d_out, int out_size)
{
    const float* x  = (const float*)d_in[0];
    const float* Wq = (const float*)d_in[1];
    const float* bq = (const float*)d_in[2];
    const float* Wk = (const float*)d_in[3];
    const float* bk = (const float*)d_in[4];
    const float* Wv = (const float*)d_in[5];
    const float* bv = (const float*)d_in[6];
    const float* Wp = (const float*)d_in[7];
    const float* bp = (const float*)d_in[8];
    float* out = (float*)d_out;

    const int ATTN_SMEM = 4 * 64 * 68 * (int)sizeof(float);  // 69632
    cudaFuncSetAttribute(attn_kernel, cudaFuncAttributeMaxDynamicSharedMemorySize, ATTN_SMEM);

    dim3 lb(256);
    dim3 lg(NTOK / 64, CC / 128);

    linear_kernel<<<lg, lb>>>(x, Wq, bq, nullptr, 0, 0);
    linear_kernel<<<lg, lb>>>(x, Wk, bk, nullptr, 0, 1);
    linear_kernel<<<lg, lb>>>(x, Wv, bv, nullptr, 0, 2);

    attn_kernel<<<dim3(TT / 64, BB * HH), 256, ATTN_SMEM>>>();

    linear_kernel<<<lg, lb>>>(nullptr, Wp, bp, out, 1, 3);
}

// round 5
// speedup vs baseline: 1.5050x; 1.5050x over previous
#include <cuda_runtime.h>
#include <cuda_bf16.h>
#include <cstdint>

#define BB 4
#define TT 2048
#define CC 1024
#define HH 16
#define DD 64
#define NTOK (BB*TT)   // 8192

// Scratch (device globals; no allocation)
__device__ float g_q[(size_t)BB*HH*TT*DD];
__device__ float g_k[(size_t)BB*HH*TT*DD];
__device__ float g_v[(size_t)BB*HH*TT*DD];
__device__ float g_y[(size_t)NTOK*CC];

// ---------------------------------------------------------------------------
// mma.sync helpers (sm_80-era PTX: valid at compute_103 base target)
// ---------------------------------------------------------------------------
__device__ __forceinline__ uint32_t smem_u32(const void* p) {
    return (uint32_t)__cvta_generic_to_shared(p);
}

__device__ __forceinline__ void ldsm4(uint32_t* r, uint32_t addr) {
    asm volatile("ldmatrix.sync.aligned.m8n8.x4.shared.b16 {%0,%1,%2,%3}, [%4];"
                 : "=r"(r[0]), "=r"(r[1]), "=r"(r[2]), "=r"(r[3]) : "r"(addr));
}

__device__ __forceinline__ void mma_bf16(float* d, const uint32_t* a, const uint32_t* b) {
    asm volatile(
        "mma.sync.aligned.m16n8k16.row.col.f32.bf16.bf16.f32 "
        "{%0,%1,%2,%3}, {%4,%5,%6,%7}, {%8,%9}, {%0,%1,%2,%3};"
        : "+f"(d[0]), "+f"(d[1]), "+f"(d[2]), "+f"(d[3])
        : "r"(a[0]), "r"(a[1]), "r"(a[2]), "r"(a[3]), "r"(b[0]), "r"(b[1]));
}

// ---------------------------------------------------------------------------
// HMMA GEMM: out[n][o] = sum_c A[n][c] * W[o][c] + bias[o]
// CTA 128x128, BK=32, 8 warps (4x2), warp tile 32x64.
// bf16 hi/lo split: D += Ah*Bh + Ah*Bl + Al*Bh  (fp32-class accuracy).
// SMEM per stage: Ah,Al,Bh,Bl each [128][40] bf16 (stride 40 => conflict-free
// ldmatrix). Double-buffered with register-prefetch pipeline.
// src_sel: 0 -> A_ext, 1 -> g_y
// dst_sel: 0/1/2 -> g_q/g_k/g_v in [B,H,T,D] layout; 3 -> out_ext row-major
// ---------------------------------------------------------------------------
#define BKC 32
#define NCH (CC / BKC)        // 32 chunks
#define ROWSTR 40             // bf16 elements per smem row
#define TILE_B (128 * ROWSTR * 2)   // 10240 bytes
#define STAGE_B (4 * TILE_B)        // 40960 bytes

__global__ __launch_bounds__(256) void mma_linear(
    const float* __restrict__ A_ext, const float* __restrict__ W,
    const float* __restrict__ bias, float* __restrict__ out_ext,
    int src_sel, int dst_sel)
{
    extern __shared__ __align__(128) char smem[];
    const uint32_t sb = smem_u32(smem);
    const int tid = threadIdx.x;
    const int wid = tid >> 5;
    const int lane = tid & 31;
    const int n0 = blockIdx.x * 128;
    const int o0 = blockIdx.y * 128;
    const float* __restrict__ A = (src_sel == 0) ? A_ext : g_y;

    const int wm = (wid >> 1) * 32;   // warp m offset (0,32,64,96)
    const int wn = (wid & 1) * 64;    // warp n offset (0,64)

    // gmem load mapping: 4 float4 for A + 4 for W per thread per chunk
    const int lrow = tid >> 3;        // used with +64*t
    const int lc4  = tid & 7;         // float4 column (0..7 -> cols 0..31)

    // ldmatrix address components
    const int ar  = wm + (lane & 15);
    const int ac8 = (lane >> 4) << 3;               // 0 or 8
    const int bn  = wn + ((lane >> 4) & 1) * 8 + (lane & 7);
    const int bc8 = ((lane >> 3) & 1) * 8;          // 0 or 8

    float acc[2][8][4];
#pragma unroll
    for (int mf = 0; mf < 2; mf++)
#pragma unroll
        for (int nf = 0; nf < 8; nf++)
#pragma unroll
            for (int e = 0; e < 4; e++) acc[mf][nf][e] = 0.f;

    float4 ra[4], rb[4];

    // ---- helpers as macros over locals ----
#define LOAD_CHUNK(k0) do {                                                   \
    _Pragma("unroll")                                                          \
    for (int t = 0; t < 4; t++) {                                              \
        const int row = lrow + t * 32;                                         \
        ra[t] = *(const float4*)(A + (size_t)(n0 + row) * CC + (k0) + lc4*4);  \
        rb[t] = *(const float4*)(W + (size_t)(o0 + row) * CC + (k0) + lc4*4);  \
    }                                                                          \
} while (0)

#define SPLIT_STORE(vv, hoff, loff) do {                                       \
    uint32_t u0 = __float_as_uint((vv).x), u1 = __float_as_uint((vv).y);       \
    uint32_t u2 = __float_as_uint((vv).z), u3 = __float_as_uint((vv).w);       \
    uint32_t h01 = __byte_perm(u0, u1, 0x7632);                                \
    uint32_t h23 = __byte_perm(u2, u3, 0x7632);                                \
    float l0 = (vv).x - __uint_as_float(u0 & 0xFFFF0000u);                     \
    float l1 = (vv).y - __uint_as_float(u1 & 0xFFFF0000u);                     \
    float l2 = (vv).z - __uint_as_float(u2 & 0xFFFF0000u);                     \
    float l3 = (vv).w - __uint_as_float(u3 & 0xFFFF0000u);                     \
    __nv_bfloat162 p01 = __floats2bfloat162_rn(l0, l1);                        \
    __nv_bfloat162 p23 = __floats2bfloat162_rn(l2, l3);                        \
    *(uint2*)(smem + (hoff)) = make_uint2(h01, h23);                           \
    *(uint2*)(smem + (loff)) = make_uint2(*reinterpret_cast<uint32_t*>(&p01),  \
                                          *reinterpret_cast<uint32_t*>(&p23)); \
} while (0)

#define STORE_CHUNK(sbase) do {                                                \
    _Pragma("unroll")                                                          \
    for (int t = 0; t < 4; t++) {                                              \
        const int row = lrow + t * 32;                                         \
        const uint32_t off = (uint32_t)(row * (ROWSTR*2) + lc4 * 8);           \
        SPLIT_STORE(ra[t], (sbase) + off, (sbase) + TILE_B + off);             \
        SPLIT_STORE(rb[t], (sbase) + 2*TILE_B + off, (sbase) + 3*TILE_B + off);\
    }                                                                          \
} while (0)

#define COMPUTE(stagebase) do {                                                \
    _Pragma("unroll")                                                          \
    for (int kk = 0; kk < 2; kk++) {                                           \
        uint32_t ah[2][4], al[2][4], bh[4][4], bl[4][4];                       \
        _Pragma("unroll")                                                      \
        for (int mf = 0; mf < 2; mf++) {                                       \
            uint32_t aoff = (uint32_t)((ar + mf*16) * (ROWSTR*2)               \
                                       + (kk*16 + ac8) * 2);                   \
            ldsm4(ah[mf], (stagebase) + aoff);                                 \
            ldsm4(al[mf], (stagebase) + TILE_B + aoff);                        \
        }                                                                      \
        _Pragma("unroll")                                                      \
        for (int p = 0; p < 4; p++) {                                          \
            uint32_t boff = (uint32_t)((bn + p*16) * (ROWSTR*2)                \
                                       + (kk*16 + bc8) * 2);                   \
            ldsm4(bh[p], (stagebase) + 2*TILE_B + boff);                       \
            ldsm4(bl[p], (stagebase) + 3*TILE_B + boff);                       \
        }                                                                      \
        _Pragma("unroll")                                                      \
        for (int mf = 0; mf < 2; mf++)                                         \
            _Pragma("unroll")                                                  \
            for (int p = 0; p < 4; p++) {                                      \
                mma_bf16(acc[mf][2*p],   ah[mf], &bh[p][0]);                   \
                mma_bf16(acc[mf][2*p+1], ah[mf], &bh[p][2]);                   \
                mma_bf16(acc[mf][2*p],   al[mf], &bh[p][0]);                   \
                mma_bf16(acc[mf][2*p+1], al[mf], &bh[p][2]);                   \
                mma_bf16(acc[mf][2*p],   ah[mf], &bl[p][0]);                   \
                mma_bf16(acc[mf][2*p+1], ah[mf], &bl[p][2]);                   \
            }                                                                  \
    }                                                                          \
} while (0)

    // ---- pipeline ----
    LOAD_CHUNK(0);
    STORE_CHUNK(0u);
    __syncthreads();

    for (int i = 0; i < NCH; i++) {
        const uint32_t cur = (uint32_t)((i & 1) * STAGE_B);
        if (i < NCH - 1) LOAD_CHUNK((i + 1) * BKC);
        COMPUTE(sb + cur);
        if (i < NCH - 1) {
            const uint32_t nxt = (uint32_t)(((i + 1) & 1) * STAGE_B);
            STORE_CHUNK(nxt);
        }
        __syncthreads();
    }

    // ---- epilogue ----
    const int g = lane >> 2;
    const int tg = lane & 3;
#pragma unroll
    for (int mf = 0; mf < 2; mf++) {
#pragma unroll
        for (int nf = 0; nf < 8; nf++) {
            const int col = o0 + wn + nf * 8 + tg * 2;
            const float b0 = __ldg(&bias[col]);
            const float b1 = __ldg(&bias[col + 1]);
#pragma unroll
            for (int hrow = 0; hrow < 2; hrow++) {
                const int n = n0 + wm + mf * 16 + g + hrow * 8;
                const float v0 = acc[mf][nf][hrow * 2 + 0] + b0;
                const float v1 = acc[mf][nf][hrow * 2 + 1] + b1;
                if (dst_sel == 3) {
                    *(float2*)(out_ext + (size_t)n * CC + col) = make_float2(v0, v1);
                } else {
                    float* __restrict__ qkv = (dst_sel == 0) ? g_q
                                            : (dst_sel == 1) ? g_k : g_v;
                    const int b = n >> 11, t = n & (TT - 1);
                    const int h = col >> 6, d = col & 63;
                    *(float2*)(qkv + (((size_t)(b * HH + h) * TT + t) << 6) + d)
                        = make_float2(v0, v1);
                }
            }
        }
    }
#undef LOAD_CHUNK
#undef SPLIT_STORE
#undef STORE_CHUNK
#undef COMPUTE
}

// ---------------------------------------------------------------------------
// Flash attention, fp32, causal (unchanged from R1 passing version).
// ---------------------------------------------------------------------------
__global__ __launch_bounds__(256) void attn_kernel()
{
    extern __shared__ float fsmem[];
    float* Qs = fsmem;
    float* Ks = Qs + 64 * 68;
    float* Vs = Ks + 64 * 68;
    float* Ps = Vs + 64 * 68;

    const int tid = threadIdx.x;
    const int tx = tid & 15;
    const int ty = tid >> 4;
    const int qi = blockIdx.x;
    const int bh = blockIdx.y;
    const int q0 = qi * 64;

    const float* __restrict__ Qp = g_q + (size_t)bh * TT * DD;
    const float* __restrict__ Kp = g_k + (size_t)bh * TT * DD;
    const float* __restrict__ Vp = g_v + (size_t)bh * TT * DD;

    const int ldn = tid >> 2;
    const int ldk0 = (tid & 3) * 4;

#pragma unroll
    for (int cg = 0; cg < 4; cg++) {
        int kk = ldk0 + cg * 16;
        float4 v = *(const float4*)(Qp + (size_t)(q0 + ldn) * DD + kk);
        Qs[(kk + 0) * 68 + ldn] = v.x; Qs[(kk + 1) * 68 + ldn] = v.y;
        Qs[(kk + 2) * 68 + ldn] = v.z; Qs[(kk + 3) * 68 + ldn] = v.w;
    }

    float m_i[4], l_i[4], acc[4][4];
#pragma unroll
    for (int i = 0; i < 4; i++) {
        m_i[i] = -3.4e38f; l_i[i] = 0.f;
#pragma unroll
        for (int j = 0; j < 4; j++) acc[i][j] = 0.f;
    }

    for (int kt = 0; kt <= qi; kt++) {
        const int k0 = kt * 64;
        __syncthreads();

#pragma unroll
        for (int cg = 0; cg < 4; cg++) {
            int kk = ldk0 + cg * 16;
            float4 kv = *(const float4*)(Kp + (size_t)(k0 + ldn) * DD + kk);
            Ks[(kk + 0) * 68 + ldn] = kv.x; Ks[(kk + 1) * 68 + ldn] = kv.y;
            Ks[(kk + 2) * 68 + ldn] = kv.z; Ks[(kk + 3) * 68 + ldn] = kv.w;
            float4 vv = *(const float4*)(Vp + (size_t)(k0 + ldn) * DD + kk);
            *(float4*)&Vs[ldn * 68 + kk] = vv;
        }
        __syncthreads();

        float s[4][4];
#pragma unroll
        for (int i = 0; i < 4; i++)
#pragma unroll
            for (int j = 0; j < 4; j++) s[i][j] = 0.f;

#pragma unroll 8
        for (int kk = 0; kk < 64; kk++) {
            float4 a = *(const float4*)&Qs[kk * 68 + ty * 4];
            float4 b = *(const float4*)&Ks[kk * 68 + tx * 4];
            float av[4] = {a.x, a.y, a.z, a.w};
            float bv[4] = {b.x, b.y, b.z, b.w};
#pragma unroll
            for (int i = 0; i < 4; i++)
#pragma unroll
                for (int j = 0; j < 4; j++)
                    s[i][j] += av[i] * bv[j];
        }

        const bool diag = (kt == qi);
#pragma unroll
        for (int i = 0; i < 4; i++)
#pragma unroll
            for (int j = 0; j < 4; j++) {
                s[i][j] *= 0.125f;
                if (diag && (tx * 4 + j > ty * 4 + i)) s[i][j] = -3.0e38f;
            }

#pragma unroll
        for (int i = 0; i < 4; i++) {
            float mx = fmaxf(fmaxf(s[i][0], s[i][1]), fmaxf(s[i][2], s[i][3]));
#pragma unroll
            for (int off = 8; off > 0; off >>= 1)
                mx = fmaxf(mx, __shfl_xor_sync(0xffffffffu, mx, off));
            float mnew = fmaxf(m_i[i], mx);
            float fac = __expf(m_i[i] - mnew);
            float rs = 0.f;
#pragma unroll
            for (int j = 0; j < 4; j++) {
                float p = __expf(s[i][j] - mnew);
                s[i][j] = p;
                rs += p;
            }
#pragma unroll
            for (int off = 8; off > 0; off >>= 1)
                rs += __shfl_xor_sync(0xffffffffu, rs, off);
            l_i[i] = l_i[i] * fac + rs;
            m_i[i] = mnew;
#pragma unroll
            for (int j = 0; j < 4; j++) acc[i][j] *= fac;
        }

#pragma unroll
        for (int i = 0; i < 4; i++)
#pragma unroll
            for (int j = 0; j < 4; j++)
                Ps[(tx * 4 + j) * 68 + ty * 4 + i] = s[i][j];
        __syncthreads();

#pragma unroll 8
        for (int kk = 0; kk < 64; kk++) {
            float4 a = *(const float4*)&Ps[kk * 68 + ty * 4];
            float4 b = *(const float4*)&Vs[kk * 68 + tx * 4];
            float av[4] = {a.x, a.y, a.z, a.w};
            float bv[4] = {b.x, b.y, b.z, b.w};
#pragma unroll
            for (int i = 0; i < 4; i++)
#pragma unroll
                for (int j = 0; j < 4; j++)
                    acc[i][j] += av[i] * bv[j];
        }
    }

    const int b = bh >> 4, h = bh & 15;
#pragma unroll
    for (int i = 0; i < 4; i++) {
        int tq = q0 + ty * 4 + i;
        float inv = 1.f / l_i[i];
#pragma unroll
        for (int j = 0; j < 4; j++)
            g_y[(size_t)(b * TT + tq) * CC + h * 64 + tx * 4 + j] = acc[i][j] * inv;
    }
}

// ---------------------------------------------------------------------------
extern "C" void kernel_launch(void* const* d_in, const int* in_sizes, int n_in,
                              void* d_out, int out_size)
{
    const float* x  = (const float*)d_in[0];
    const float* Wq = (const float*)d_in[1];
    const float* bq = (const float*)d_in[2];
    const float* Wk = (const float*)d_in[3];
    const float* bk = (const float*)d_in[4];
    const float* Wv = (const float*)d_in[5];
    const float* bv = (const float*)d_in[6];
    const float* Wp = (const float*)d_in[7];
    const float* bp = (const float*)d_in[8];
    float* out = (float*)d_out;

    const int GEMM_SMEM = 2 * STAGE_B;  // 81920
    cudaFuncSetAttribute(mma_linear, cudaFuncAttributeMaxDynamicSharedMemorySize, GEMM_SMEM);
    const int ATTN_SMEM = 4 * 64 * 68 * (int)sizeof(float);  // 69632
    cudaFuncSetAttribute(attn_kernel, cudaFuncAttributeMaxDynamicSharedMemorySize, ATTN_SMEM);

    dim3 gb(256);
    dim3 gg(NTOK / 128, CC / 128);  // 64 x 8

    mma_linear<<<gg, gb, GEMM_SMEM>>>(x, Wq, bq, nullptr, 0, 0);
    mma_linear<<<gg, gb, GEMM_SMEM>>>(x, Wk, bk, nullptr, 0, 1);
    mma_linear<<<gg, gb, GEMM_SMEM>>>(x, Wv, bv, nullptr, 0, 2);

    attn_kernel<<<dim3(TT / 64, BB * HH), 256, ATTN_SMEM>>>();

    mma_linear<<<gg, gb, GEMM_SMEM>>>(nullptr, Wp, bp, out, 1, 3);
}

// round 8
// speedup vs baseline: 2.6300x; 1.7475x over previous
#include <cuda_runtime.h>
#include <cuda_bf16.h>
#include <cstdint>

#define BB 4
#define TT 2048
#define CC 1024
#define HH 16
#define DD 64
#define NTOK (BB*TT)   // 8192

// Scratch (device globals; no allocation)
__device__ float g_q[(size_t)BB*HH*TT*DD];
__device__ float g_k[(size_t)BB*HH*TT*DD];
__device__ float g_v[(size_t)BB*HH*TT*DD];
__device__ float g_y[(size_t)NTOK*CC];

// ---------------------------------------------------------------------------
// mma.sync helpers (sm_80-era PTX: valid at compute_103 base target)
// ---------------------------------------------------------------------------
__device__ __forceinline__ uint32_t smem_u32(const void* p) {
    return (uint32_t)__cvta_generic_to_shared(p);
}

__device__ __forceinline__ void ldsm4(uint32_t* r, uint32_t addr) {
    asm volatile("ldmatrix.sync.aligned.m8n8.x4.shared.b16 {%0,%1,%2,%3}, [%4];"
                 : "=r"(r[0]), "=r"(r[1]), "=r"(r[2]), "=r"(r[3]) : "r"(addr));
}

__device__ __forceinline__ void ldsm4t(uint32_t* r, uint32_t addr) {
    asm volatile("ldmatrix.sync.aligned.m8n8.x4.trans.shared.b16 {%0,%1,%2,%3}, [%4];"
                 : "=r"(r[0]), "=r"(r[1]), "=r"(r[2]), "=r"(r[3]) : "r"(addr));
}

__device__ __forceinline__ void mma_bf16(float* d, const uint32_t* a, const uint32_t* b) {
    asm volatile(
        "mma.sync.aligned.m16n8k16.row.col.f32.bf16.bf16.f32 "
        "{%0,%1,%2,%3}, {%4,%5,%6,%7}, {%8,%9}, {%0,%1,%2,%3};"
        : "+f"(d[0]), "+f"(d[1]), "+f"(d[2]), "+f"(d[3])
        : "r"(a[0]), "r"(a[1]), "r"(a[2]), "r"(a[3]), "r"(b[0]), "r"(b[1]));
}

// split two fp32 into packed bf16-hi pair + packed bf16-lo pair
__device__ __forceinline__ void split2(float x, float y, uint32_t& hp, uint32_t& lp) {
    uint32_t ux = __float_as_uint(x), uy = __float_as_uint(y);
    hp = __byte_perm(ux, uy, 0x7632);
    float lx = x - __uint_as_float(ux & 0xFFFF0000u);
    float ly = y - __uint_as_float(uy & 0xFFFF0000u);
    __nv_bfloat162 pl = __floats2bfloat162_rn(lx, ly);
    lp = *reinterpret_cast<uint32_t*>(&pl);
}

// split a float4 and store packed hi (uint2) at hoff, lo at loff (byte offsets)
__device__ __forceinline__ void split_store(char* smem, float4 v, uint32_t hoff, uint32_t loff) {
    uint32_t h01, l01, h23, l23;
    split2(v.x, v.y, h01, l01);
    split2(v.z, v.w, h23, l23);
    *(uint2*)(smem + hoff) = make_uint2(h01, h23);
    *(uint2*)(smem + loff) = make_uint2(l01, l23);
}

// ---------------------------------------------------------------------------
// HMMA GEMM: out[n][o] = sum_c A[n][c] * W[o][c] + bias[o]   (unchanged R5)
// ---------------------------------------------------------------------------
#define BKC 32
#define NCH (CC / BKC)        // 32 chunks
#define ROWSTR 40             // bf16 elements per smem row (BK=32 tile)
#define ROWB (ROWSTR*2)       // 80 bytes
#define TILE_B (128 * ROWB)   // 10240 bytes
#define STAGE_B (4 * TILE_B)  // 40960 bytes

__global__ __launch_bounds__(256) void mma_linear(
    const float* __restrict__ A_ext, const float* __restrict__ W,
    const float* __restrict__ bias, float* __restrict__ out_ext,
    int src_sel, int dst_sel)
{
    extern __shared__ __align__(128) char smem[];
    const uint32_t sb = smem_u32(smem);
    const int tid = threadIdx.x;
    const int wid = tid >> 5;
    const int lane = tid & 31;
    const int n0 = blockIdx.x * 128;
    const int o0 = blockIdx.y * 128;
    const float* __restrict__ A = (src_sel == 0) ? A_ext : g_y;

    const int wm = (wid >> 1) * 32;
    const int wn = (wid & 1) * 64;
    const int lrow = tid >> 3;
    const int lc4  = tid & 7;
    const int ar  = wm + (lane & 15);
    const int ac8 = (lane >> 4) << 3;
    const int bn  = wn + ((lane >> 4) & 1) * 8 + (lane & 7);
    const int bc8 = ((lane >> 3) & 1) * 8;

    float acc[2][8][4];
#pragma unroll
    for (int mf = 0; mf < 2; mf++)
#pragma unroll
        for (int nf = 0; nf < 8; nf++)
#pragma unroll
            for (int e = 0; e < 4; e++) acc[mf][nf][e] = 0.f;

    float4 ra[4], rb[4];

#define LOAD_CHUNK(k0) do {                                                   \
    _Pragma("unroll")                                                          \
    for (int t = 0; t < 4; t++) {                                              \
        const int row = lrow + t * 32;                                         \
        ra[t] = *(const float4*)(A + (size_t)(n0 + row) * CC + (k0) + lc4*4);  \
        rb[t] = *(const float4*)(W + (size_t)(o0 + row) * CC + (k0) + lc4*4);  \
    }                                                                          \
} while (0)

#define STORE_CHUNK(sbase) do {                                                \
    _Pragma("unroll")                                                          \
    for (int t = 0; t < 4; t++) {                                              \
        const int row = lrow + t * 32;                                         \
        const uint32_t off = (uint32_t)(row * ROWB + lc4 * 8);                 \
        split_store(smem, ra[t], (sbase) + off, (sbase) + TILE_B + off);       \
        split_store(smem, rb[t], (sbase) + 2*TILE_B + off, (sbase) + 3*TILE_B + off); \
    }                                                                          \
} while (0)

#define COMPUTE(stagebase) do {                                                \
    _Pragma("unroll")                                                          \
    for (int kk = 0; kk < 2; kk++) {                                           \
        uint32_t ah[2][4], al[2][4], bh2[4][4], bl2[4][4];                     \
        _Pragma("unroll")                                                      \
        for (int mf = 0; mf < 2; mf++) {                                       \
            uint32_t aoff = (uint32_t)((ar + mf*16) * ROWB + (kk*16 + ac8) * 2); \
            ldsm4(ah[mf], (stagebase) + aoff);                                 \
            ldsm4(al[mf], (stagebase) + TILE_B + aoff);                        \
        }                                                                      \
        _Pragma("unroll")                                                      \
        for (int p = 0; p < 4; p++) {                                          \
            uint32_t boff = (uint32_t)((bn + p*16) * ROWB + (kk*16 + bc8) * 2); \
            ldsm4(bh2[p], (stagebase) + 2*TILE_B + boff);                      \
            ldsm4(bl2[p], (stagebase) + 3*TILE_B + boff);                      \
        }                                                                      \
        _Pragma("unroll")                                                      \
        for (int mf = 0; mf < 2; mf++)                                         \
            _Pragma("unroll")                                                  \
            for (int p = 0; p < 4; p++) {                                      \
                mma_bf16(acc[mf][2*p],   ah[mf], &bh2[p][0]);                  \
                mma_bf16(acc[mf][2*p+1], ah[mf], &bh2[p][2]);                  \
                mma_bf16(acc[mf][2*p],   al[mf], &bh2[p][0]);                  \
                mma_bf16(acc[mf][2*p+1], al[mf], &bh2[p][2]);                  \
                mma_bf16(acc[mf][2*p],   ah[mf], &bl2[p][0]);                  \
                mma_bf16(acc[mf][2*p+1], ah[mf], &bl2[p][2]);                  \
            }                                                                  \
    }                                                                          \
} while (0)

    LOAD_CHUNK(0);
    STORE_CHUNK(0u);
    __syncthreads();

    for (int i = 0; i < NCH; i++) {
        const uint32_t cur = (uint32_t)((i & 1) * STAGE_B);
        if (i < NCH - 1) LOAD_CHUNK((i + 1) * BKC);
        COMPUTE(sb + cur);
        if (i < NCH - 1) {
            const uint32_t nxt = (uint32_t)(((i + 1) & 1) * STAGE_B);
            STORE_CHUNK(nxt);
        }
        __syncthreads();
    }

    const int g = lane >> 2;
    const int tg = lane & 3;
#pragma unroll
    for (int mf = 0; mf < 2; mf++) {
#pragma unroll
        for (int nf = 0; nf < 8; nf++) {
            const int col = o0 + wn + nf * 8 + tg * 2;
            const float b0 = __ldg(&bias[col]);
            const float b1 = __ldg(&bias[col + 1]);
#pragma unroll
            for (int hrow = 0; hrow < 2; hrow++) {
                const int n = n0 + wm + mf * 16 + g + hrow * 8;
                const float v0 = acc[mf][nf][hrow * 2 + 0] + b0;
                const float v1 = acc[mf][nf][hrow * 2 + 1] + b1;
                if (dst_sel == 3) {
                    *(float2*)(out_ext + (size_t)n * CC + col) = make_float2(v0, v1);
                } else {
                    float* __restrict__ qkv = (dst_sel == 0) ? g_q
                                            : (dst_sel == 1) ? g_k : g_v;
                    const int b = n >> 11, t = n & (TT - 1);
                    const int h = col >> 6, d = col & 63;
                    *(float2*)(qkv + (((size_t)(b * HH + h) * TT + t) << 6) + d)
                        = make_float2(v0, v1);
                }
            }
        }
    }
#undef LOAD_CHUNK
#undef STORE_CHUNK
#undef COMPUTE
}

// ---------------------------------------------------------------------------
// HMMA flash attention, causal. CTA = 64 queries of one (b,h). 4 warps,
// warp w owns query rows [w*16, w*16+16). Bc = 64 keys/iter, d = 64.
// bf16 hi/lo 3-MMA split on both Q*K^T and P*V (fp32-class accuracy).
// SMEM tiles [64 rows][AROWSTR=72 bf16] (d=64 cols + pad): KH,KL,VH,VL
// (Q staged in KH/KL first). 144-byte row stride => conflict-free ldmatrix.
// ---------------------------------------------------------------------------
#define AROWSTR 72
#define AROWB (AROWSTR*2)          // 144 bytes
#define ATILE_B (64 * AROWB)       // 9216 bytes
#define ATTN_SMEM_SZ (4 * ATILE_B) // 36864

__global__ __launch_bounds__(128) void attn_kernel()
{
    extern __shared__ __align__(128) char smem[];
    const uint32_t sb = smem_u32(smem);
    const int tid = threadIdx.x;
    const int wid = tid >> 5;
    const int lane = tid & 31;
    const int qi = blockIdx.x;
    const int bh = blockIdx.y;
    const int q0 = qi * 64;

    const float* __restrict__ Qp = g_q + (size_t)bh * TT * DD;
    const float* __restrict__ Kp = g_k + (size_t)bh * TT * DD;
    const float* __restrict__ Vp = g_v + (size_t)bh * TT * DD;

    const uint32_t KH = 0, KL = ATILE_B, VH = 2*ATILE_B, VL = 3*ATILE_B;

    // gmem load mapping: 64 rows x 16 float4 = 1024 float4, 8 per thread
    const int lrow = tid >> 4;        // +8*t
    const int lc4  = tid & 15;

    // ldmatrix address components
    const int ar  = wid * 16 + (lane & 15);        // A rows (queries)
    const int ac8 = (lane >> 4) << 3;
    const int bn  = ((lane >> 4) & 1) * 8 + (lane & 7);  // B rows (keys), + p*16
    const int bc8 = ((lane >> 3) & 1) * 8;
    // V trans-ldmatrix components
    const int vrow = lane & 15;                    // + kp*16 (keys)
    const int vc8  = (lane >> 4) << 3;             // + g*16 (d)

    // ---- stage Q (scaled by 1/8), build A-fragments, then free the buffer ----
    uint32_t qh[4][4], ql[4][4];
    {
#pragma unroll
        for (int t = 0; t < 8; t++) {
            const int row = lrow + t * 8;
            float4 v = *(const float4*)(Qp + (size_t)(q0 + row) * DD + lc4 * 4);
            v.x *= 0.125f; v.y *= 0.125f; v.z *= 0.125f; v.w *= 0.125f;
            const uint32_t off = (uint32_t)(row * AROWB + lc4 * 8);
            split_store(smem, v, KH + off, KL + off);
        }
        __syncthreads();
#pragma unroll
        for (int kk = 0; kk < 4; kk++) {
            const uint32_t aoff = (uint32_t)(ar * AROWB + (kk * 16 + ac8) * 2);
            ldsm4(qh[kk], sb + KH + aoff);
            ldsm4(ql[kk], sb + KL + aoff);
        }
    }

    float o[8][4];
#pragma unroll
    for (int nf = 0; nf < 8; nf++)
#pragma unroll
        for (int e = 0; e < 4; e++) o[nf][e] = 0.f;
    float m0 = -1e30f, m1 = -1e30f, l0 = 0.f, l1 = 0.f;

    const int r0 = lane >> 2;     // local row (within warp's 16)
    const int c0 = (lane & 3) * 2;

    for (int kt = 0; kt <= qi; kt++) {
        const int k0 = kt * 64;
        __syncthreads();  // previous iter's smem reads (and Q-frag build) done

        // load K,V fp32 -> bf16 hi/lo smem
#pragma unroll
        for (int t = 0; t < 8; t++) {
            const int row = lrow + t * 8;
            const uint32_t off = (uint32_t)(row * AROWB + lc4 * 8);
            float4 kv = *(const float4*)(Kp + (size_t)(k0 + row) * DD + lc4 * 4);
            split_store(smem, kv, KH + off, KL + off);
            float4 vv = *(const float4*)(Vp + (size_t)(k0 + row) * DD + lc4 * 4);
            split_store(smem, vv, VH + off, VL + off);
        }
        __syncthreads();

        // ---- S = Q K^T ----
        float s[8][4];
#pragma unroll
        for (int nf = 0; nf < 8; nf++)
#pragma unroll
            for (int e = 0; e < 4; e++) s[nf][e] = 0.f;

#pragma unroll
        for (int kk = 0; kk < 4; kk++) {
            uint32_t kh[4][4], kl[4][4];
#pragma unroll
            for (int p = 0; p < 4; p++) {
                const uint32_t boff = (uint32_t)((bn + p * 16) * AROWB + (kk * 16 + bc8) * 2);
                ldsm4(kh[p], sb + KH + boff);
                ldsm4(kl[p], sb + KL + boff);
            }
#pragma unroll
            for (int p = 0; p < 4; p++) {
                mma_bf16(s[2*p],   qh[kk], &kh[p][0]);
                mma_bf16(s[2*p+1], qh[kk], &kh[p][2]);
                mma_bf16(s[2*p],   ql[kk], &kh[p][0]);
                mma_bf16(s[2*p+1], ql[kk], &kh[p][2]);
                mma_bf16(s[2*p],   qh[kk], &kl[p][0]);
                mma_bf16(s[2*p+1], qh[kk], &kl[p][2]);
            }
        }

        // ---- causal mask (diagonal tile only) ----
        if (kt == qi) {
            const int lr0 = wid * 16 + r0;
            const int lr1 = lr0 + 8;
#pragma unroll
            for (int nf = 0; nf < 8; nf++) {
                const int lc = nf * 8 + c0;
                if (lc     > lr0) s[nf][0] = -1e30f;
                if (lc + 1 > lr0) s[nf][1] = -1e30f;
                if (lc     > lr1) s[nf][2] = -1e30f;
                if (lc + 1 > lr1) s[nf][3] = -1e30f;
            }
        }

        // ---- online softmax (rows r0 and r0+8) ----
        float mx0 = -1e30f, mx1 = -1e30f;
#pragma unroll
        for (int nf = 0; nf < 8; nf++) {
            mx0 = fmaxf(mx0, fmaxf(s[nf][0], s[nf][1]));
            mx1 = fmaxf(mx1, fmaxf(s[nf][2], s[nf][3]));
        }
        mx0 = fmaxf(mx0, __shfl_xor_sync(0xffffffffu, mx0, 1));
        mx0 = fmaxf(mx0, __shfl_xor_sync(0xffffffffu, mx0, 2));
        mx1 = fmaxf(mx1, __shfl_xor_sync(0xffffffffu, mx1, 1));
        mx1 = fmaxf(mx1, __shfl_xor_sync(0xffffffffu, mx1, 2));

        const float mn0 = fmaxf(m0, mx0);
        const float mn1 = fmaxf(m1, mx1);
        const float fac0 = __expf(m0 - mn0);
        const float fac1 = __expf(m1 - mn1);
        m0 = mn0; m1 = mn1;

        float rs0 = 0.f, rs1 = 0.f;
#pragma unroll
        for (int nf = 0; nf < 8; nf++) {
            s[nf][0] = __expf(s[nf][0] - mn0);
            s[nf][1] = __expf(s[nf][1] - mn0);
            s[nf][2] = __expf(s[nf][2] - mn1);
            s[nf][3] = __expf(s[nf][3] - mn1);
            rs0 += s[nf][0] + s[nf][1];
            rs1 += s[nf][2] + s[nf][3];
        }
        rs0 += __shfl_xor_sync(0xffffffffu, rs0, 1);
        rs0 += __shfl_xor_sync(0xffffffffu, rs0, 2);
        rs1 += __shfl_xor_sync(0xffffffffu, rs1, 1);
        rs1 += __shfl_xor_sync(0xffffffffu, rs1, 2);
        l0 = l0 * fac0 + rs0;
        l1 = l1 * fac1 + rs1;

#pragma unroll
        for (int nf = 0; nf < 8; nf++) {
            o[nf][0] *= fac0; o[nf][1] *= fac0;
            o[nf][2] *= fac1; o[nf][3] *= fac1;
        }

        // ---- O += P V ----
#pragma unroll
        for (int kp = 0; kp < 4; kp++) {
            uint32_t pa_h[4], pa_l[4];
            split2(s[2*kp][0],   s[2*kp][1],   pa_h[0], pa_l[0]);
            split2(s[2*kp][2],   s[2*kp][3],   pa_h[1], pa_l[1]);
            split2(s[2*kp+1][0], s[2*kp+1][1], pa_h[2], pa_l[2]);
            split2(s[2*kp+1][2], s[2*kp+1][3], pa_h[3], pa_l[3]);
#pragma unroll
            for (int gg = 0; gg < 4; gg++) {
                uint32_t vh[4], vl[4];
                const uint32_t voff = (uint32_t)((kp * 16 + vrow) * AROWB + (gg * 16 + vc8) * 2);
                ldsm4t(vh, sb + VH + voff);
                ldsm4t(vl, sb + VL + voff);
                mma_bf16(o[2*gg],   pa_h, &vh[0]);
                mma_bf16(o[2*gg+1], pa_h, &vh[2]);
                mma_bf16(o[2*gg],   pa_l, &vh[0]);
                mma_bf16(o[2*gg+1], pa_l, &vh[2]);
                mma_bf16(o[2*gg],   pa_h, &vl[0]);
                mma_bf16(o[2*gg+1], pa_h, &vl[2]);
            }
        }
    }

    // ---- epilogue: y[b][t][h*64+d] ----
    const int b = bh >> 4, h = bh & 15;
    const float inv0 = 1.f / l0;
    const float inv1 = 1.f / l1;
    const int rg0 = q0 + wid * 16 + r0;
    const int rg1 = rg0 + 8;
#pragma unroll
    for (int nf = 0; nf < 8; nf++) {
        const int col = h * 64 + nf * 8 + c0;
        *(float2*)(g_y + (size_t)(b * TT + rg0) * CC + col)
            = make_float2(o[nf][0] * inv0, o[nf][1] * inv0);
        *(float2*)(g_y + (size_t)(b * TT + rg1) * CC + col)
            = make_float2(o[nf][2] * inv1, o[nf][3] * inv1);
    }
}

// ---------------------------------------------------------------------------
extern "C" void kernel_launch(void* const* d_in, const int* in_sizes, int n_in,
                              void* d_out, int out_size)
{
    const float* x  = (const float*)d_in[0];
    const float* Wq = (const float*)d_in[1];
    const float* bq = (const float*)d_in[2];
    const float* Wk = (const float*)d_in[3];
    const float* bk = (const float*)d_in[4];
    const float* Wv = (const float*)d_in[5];
    const float* bv = (const float*)d_in[6];
    const float* Wp = (const float*)d_in[7];
    const float* bp = (const float*)d_in[8];
    float* out = (float*)d_out;

    const int GEMM_SMEM = 2 * STAGE_B;  // 81920
    cudaFuncSetAttribute(mma_linear, cudaFuncAttributeMaxDynamicSharedMemorySize, GEMM_SMEM);
    cudaFuncSetAttribute(attn_kernel, cudaFuncAttributeMaxDynamicSharedMemorySize, ATTN_SMEM_SZ);

    dim3 gb(256);
    dim3 gg(NTOK / 128, CC / 128);  // 64 x 8

    mma_linear<<<gg, gb, GEMM_SMEM>>>(x, Wq, bq, nullptr, 0, 0);
    mma_linear<<<gg, gb, GEMM_SMEM>>>(x, Wk, bk, nullptr, 0, 1);
    mma_linear<<<gg, gb, GEMM_SMEM>>>(x, Wv, bv, nullptr, 0, 2);

    attn_kernel<<<dim3(TT / 64, BB * HH), 128, ATTN_SMEM_SZ>>>();

    mma_linear<<<gg, gb, GEMM_SMEM>>>(nullptr, Wp, bp, out, 1, 3);
}

// round 9
// speedup vs baseline: 3.0926x; 1.1759x over previous
#include <cuda_runtime.h>
#include <cuda_bf16.h>
#include <cstdint>

#define BB 4
#define TT 2048
#define CC 1024
#define HH 16
#define DD 64
#define NTOK (BB*TT)   // 8192
#define NELEM ((size_t)NTOK*CC)   // 8388608 == BB*HH*TT*DD

// Persistent bf16 hi/lo scratch (device globals; no allocation)
__device__ __align__(16) uint16_t g_xh[NELEM], g_xl[NELEM];
__device__ __align__(16) uint16_t g_wh[(size_t)4*CC*CC], g_wl[(size_t)4*CC*CC];
__device__ __align__(16) uint16_t g_qh[NELEM], g_ql[NELEM];
__device__ __align__(16) uint16_t g_kh[NELEM], g_kl[NELEM];
__device__ __align__(16) uint16_t g_vh[NELEM], g_vl[NELEM];
__device__ __align__(16) uint16_t g_yh[NELEM], g_yl[NELEM];

// ---------------------------------------------------------------------------
// helpers (sm_80-era PTX: valid at compute_103 base target)
// ---------------------------------------------------------------------------
__device__ __forceinline__ uint32_t smem_u32(const void* p) {
    return (uint32_t)__cvta_generic_to_shared(p);
}

__device__ __forceinline__ void ldsm4(uint32_t* r, uint32_t addr) {
    asm volatile("ldmatrix.sync.aligned.m8n8.x4.shared.b16 {%0,%1,%2,%3}, [%4];"
                 : "=r"(r[0]), "=r"(r[1]), "=r"(r[2]), "=r"(r[3]) : "r"(addr));
}

__device__ __forceinline__ void ldsm4t(uint32_t* r, uint32_t addr) {
    asm volatile("ldmatrix.sync.aligned.m8n8.x4.trans.shared.b16 {%0,%1,%2,%3}, [%4];"
                 : "=r"(r[0]), "=r"(r[1]), "=r"(r[2]), "=r"(r[3]) : "r"(addr));
}

__device__ __forceinline__ void mma_bf16(float* d, const uint32_t* a, const uint32_t* b) {
    asm volatile(
        "mma.sync.aligned.m16n8k16.row.col.f32.bf16.bf16.f32 "
        "{%0,%1,%2,%3}, {%4,%5,%6,%7}, {%8,%9}, {%0,%1,%2,%3};"
        : "+f"(d[0]), "+f"(d[1]), "+f"(d[2]), "+f"(d[3])
        : "r"(a[0]), "r"(a[1]), "r"(a[2]), "r"(a[3]), "r"(b[0]), "r"(b[1]));
}

__device__ __forceinline__ void split2(float x, float y, uint32_t& hp, uint32_t& lp) {
    uint32_t ux = __float_as_uint(x), uy = __float_as_uint(y);
    hp = __byte_perm(ux, uy, 0x7632);
    float lx = x - __uint_as_float(ux & 0xFFFF0000u);
    float ly = y - __uint_as_float(uy & 0xFFFF0000u);
    __nv_bfloat162 pl = __floats2bfloat162_rn(lx, ly);
    lp = *reinterpret_cast<uint32_t*>(&pl);
}

#define CP_ASYNC16(dst, src) \
    asm volatile("cp.async.cg.shared.global [%0], [%1], 16;" :: "r"(dst), "l"(src))
#define CP_COMMIT asm volatile("cp.async.commit_group;")
#define CP_WAIT0 asm volatile("cp.async.wait_group 0;")
#define CP_WAIT1 asm volatile("cp.async.wait_group 1;")

// ---------------------------------------------------------------------------
// Pre-split pass: fp32 -> bf16 hi/lo. dsel: 0 -> x, 1..4 -> W slot (dsel-1)
// ---------------------------------------------------------------------------
__global__ __launch_bounds__(256) void split_kernel(
    const float* __restrict__ src, int dsel, int n4)
{
    int i = blockIdx.x * blockDim.x + threadIdx.x;
    if (i >= n4) return;
    uint2* dh;
    uint2* dl;
    if (dsel == 0) { dh = (uint2*)g_xh; dl = (uint2*)g_xl; }
    else {
        dh = (uint2*)(g_wh + (size_t)(dsel - 1) * CC * CC);
        dl = (uint2*)(g_wl + (size_t)(dsel - 1) * CC * CC);
    }
    float4 v = ((const float4*)src)[i];
    uint32_t h01, l01, h23, l23;
    split2(v.x, v.y, h01, l01);
    split2(v.z, v.w, h23, l23);
    dh[i] = make_uint2(h01, h23);
    dl[i] = make_uint2(l01, l23);
}

// ---------------------------------------------------------------------------
// HMMA GEMM v2: out[n][o] = sum_c A[n][c]*W[o][c] + bias[o]
// Inputs pre-split bf16 hi/lo. cp.async 3-stage pipeline, BK=32.
// SMEM tile: 128 rows x 64B, XOR swizzle pc = c ^ ((row>>1)&3) (conflict-free).
// asel: 0 -> x, 1 -> y. wsel: 0..3 weight slot.
// dst_sel: 0/1/2 -> q/k/v hi/lo [B,H,T,D] (Q scaled 0.125); 3 -> fp32 out.
// ---------------------------------------------------------------------------
#define BKC 32
#define NCH (CC / BKC)           // 32
#define GS_TILE 8192             // 128 * 64B
#define GS_STAGE (4 * GS_TILE)   // 32768
#define G_SMEM (3 * GS_STAGE)    // 98304

__global__ __launch_bounds__(256) void mma_linear(
    int asel, int wsel, const float* __restrict__ bias,
    float* __restrict__ out_ext, int dst_sel)
{
    extern __shared__ __align__(128) char smem[];
    const uint32_t sb = smem_u32(smem);
    const int tid = threadIdx.x;
    const int wid = tid >> 5;
    const int lane = tid & 31;
    const int n0 = blockIdx.x * 128;
    const int o0 = blockIdx.y * 128;

    const uint16_t* __restrict__ Ah = asel ? g_yh : g_xh;
    const uint16_t* __restrict__ Al = asel ? g_yl : g_xl;
    const uint16_t* __restrict__ Wh = g_wh + (size_t)wsel * CC * CC;
    const uint16_t* __restrict__ Wl = g_wl + (size_t)wsel * CC * CC;

    const int wm = (wid >> 1) * 32;
    const int wn = (wid & 1) * 64;
    const int ar  = wm + (lane & 15);
    const int ak  = (lane >> 4);                  // k-chunk half: 0/1
    const int bn  = wn + ((lane >> 4) & 1) * 8 + (lane & 7);
    const int bk  = ((lane >> 3) & 1);

    float acc[2][8][4];
#pragma unroll
    for (int mf = 0; mf < 2; mf++)
#pragma unroll
        for (int nf = 0; nf < 8; nf++)
#pragma unroll
            for (int e = 0; e < 4; e++) acc[mf][nf][e] = 0.f;

#define G_ISSUE(i, s) do {                                                     \
    const int _k0 = (i) * BKC;                                                 \
    const uint32_t _stb = sb + (uint32_t)(s) * GS_STAGE;                       \
    _Pragma("unroll")                                                          \
    for (int t = 0; t < 8; t++) {                                              \
        const int tile = t >> 1;                                               \
        const int idx2 = tid + (t & 1) * 256;                                  \
        const int row = idx2 >> 2, cc = idx2 & 3;                              \
        const uint32_t dst = _stb + tile * GS_TILE + row * 64                  \
                             + ((cc ^ ((row >> 1) & 3)) << 4);                 \
        const uint16_t* srcp;                                                  \
        if (tile == 0)      srcp = Ah + (size_t)(n0 + row) * CC + _k0 + cc * 8;\
        else if (tile == 1) srcp = Al + (size_t)(n0 + row) * CC + _k0 + cc * 8;\
        else if (tile == 2) srcp = Wh + (size_t)(o0 + row) * CC + _k0 + cc * 8;\
        else                srcp = Wl + (size_t)(o0 + row) * CC + _k0 + cc * 8;\
        CP_ASYNC16(dst, srcp);                                                 \
    }                                                                          \
    CP_COMMIT;                                                                 \
} while (0)

#define G_COMPUTE(stagebase) do {                                              \
    _Pragma("unroll")                                                          \
    for (int kk = 0; kk < 2; kk++) {                                           \
        uint32_t ah[2][4], al[2][4], bh2[4][4], bl2[4][4];                     \
        _Pragma("unroll")                                                      \
        for (int mf = 0; mf < 2; mf++) {                                       \
            const int r = ar + mf * 16;                                        \
            const int c = kk * 2 + ak;                                         \
            const uint32_t aoff = (uint32_t)(r * 64 + ((c ^ ((r >> 1) & 3)) << 4)); \
            ldsm4(ah[mf], (stagebase) + aoff);                                 \
            ldsm4(al[mf], (stagebase) + GS_TILE + aoff);                       \
        }                                                                      \
        _Pragma("unroll")                                                      \
        for (int p = 0; p < 4; p++) {                                          \
            const int r = bn + p * 16;                                         \
            const int c = kk * 2 + bk;                                         \
            const uint32_t boff = (uint32_t)(r * 64 + ((c ^ ((r >> 1) & 3)) << 4)); \
            ldsm4(bh2[p], (stagebase) + 2 * GS_TILE + boff);                   \
            ldsm4(bl2[p], (stagebase) + 3 * GS_TILE + boff);                   \
        }                                                                      \
        _Pragma("unroll")                                                      \
        for (int mf = 0; mf < 2; mf++)                                         \
            _Pragma("unroll")                                                  \
            for (int p = 0; p < 4; p++) {                                      \
                mma_bf16(acc[mf][2*p],   ah[mf], &bh2[p][0]);                  \
                mma_bf16(acc[mf][2*p+1], ah[mf], &bh2[p][2]);                  \
                mma_bf16(acc[mf][2*p],   al[mf], &bh2[p][0]);                  \
                mma_bf16(acc[mf][2*p+1], al[mf], &bh2[p][2]);                  \
                mma_bf16(acc[mf][2*p],   ah[mf], &bl2[p][0]);                  \
                mma_bf16(acc[mf][2*p+1], ah[mf], &bl2[p][2]);                  \
            }                                                                  \
    }                                                                          \
} while (0)

    G_ISSUE(0, 0);
    G_ISSUE(1, 1);

    for (int i = 0; i < NCH; i++) {
        if (i == NCH - 1) { CP_WAIT0; } else { CP_WAIT1; }
        __syncthreads();
        if (i + 2 < NCH) {
            const int s2 = (i + 2) % 3;
            G_ISSUE(i + 2, s2);
        }
        G_COMPUTE(sb + (uint32_t)(i % 3) * GS_STAGE);
    }

    // epilogue
    const int g = lane >> 2;
    const int tg = lane & 3;
#pragma unroll
    for (int mf = 0; mf < 2; mf++) {
#pragma unroll
        for (int nf = 0; nf < 8; nf++) {
            const int col = o0 + wn + nf * 8 + tg * 2;
            const float b0 = __ldg(&bias[col]);
            const float b1 = __ldg(&bias[col + 1]);
#pragma unroll
            for (int hrow = 0; hrow < 2; hrow++) {
                const int n = n0 + wm + mf * 16 + g + hrow * 8;
                float v0 = acc[mf][nf][hrow * 2 + 0] + b0;
                float v1 = acc[mf][nf][hrow * 2 + 1] + b1;
                if (dst_sel == 3) {
                    *(float2*)(out_ext + (size_t)n * CC + col) = make_float2(v0, v1);
                } else {
                    if (dst_sel == 0) { v0 *= 0.125f; v1 *= 0.125f; }
                    uint32_t hp, lp;
                    split2(v0, v1, hp, lp);
                    const int b = n >> 11, t = n & (TT - 1);
                    const int h = col >> 6, d = col & 63;
                    const size_t idx = (((size_t)(b * HH + h) * TT + t) << 6) + d;
                    uint16_t* dsth = (dst_sel == 0) ? g_qh : (dst_sel == 1) ? g_kh : g_vh;
                    uint16_t* dstl = (dst_sel == 0) ? g_ql : (dst_sel == 1) ? g_kl : g_vl;
                    *(uint32_t*)(dsth + idx) = hp;
                    *(uint32_t*)(dstl + idx) = lp;
                }
            }
        }
    }
#undef G_ISSUE
#undef G_COMPUTE
}

// ---------------------------------------------------------------------------
// HMMA flash attention v2, causal. CTA = 64 queries of one (b,h), 4 warps.
// Pre-split bf16 K/V/Q loaded via cp.async, double-buffered K/V stages.
// SMEM rows: 64 cols bf16 + pad, 144B stride (conflict-free ldmatrix).
// qi reversed so heavy tiles launch first.
// ---------------------------------------------------------------------------
#define AROWB 144
#define ATILE_B (64 * AROWB)          // 9216
#define A_STAGE (4 * ATILE_B)         // 36864
#define A_SMEM (2 * ATILE_B + 2 * A_STAGE)  // 92160

__global__ __launch_bounds__(128) void attn_kernel()
{
    extern __shared__ __align__(128) char smem[];
    const uint32_t sb = smem_u32(smem);
    const int tid = threadIdx.x;
    const int wid = tid >> 5;
    const int lane = tid & 31;
    const int qi = gridDim.x - 1 - blockIdx.x;   // heavy tiles first
    const int bh = blockIdx.y;
    const int q0 = qi * 64;
    const size_t bhbase = (size_t)bh * TT;

    // ldmatrix address components
    const int ar  = wid * 16 + (lane & 15);
    const int ac8 = (lane >> 4) << 3;
    const int bn  = ((lane >> 4) & 1) * 8 + (lane & 7);
    const int bc8 = ((lane >> 3) & 1) * 8;
    const int vrow = lane & 15;
    const int vc8  = (lane >> 4) << 3;

#define A_ISSUE_Q do {                                                         \
    _Pragma("unroll")                                                          \
    for (int t = 0; t < 8; t++) {                                              \
        const int tile = t >> 2;                                               \
        const int idx2 = tid + (t & 3) * 128;                                  \
        const int row = idx2 >> 3, cc = idx2 & 7;                              \
        const uint32_t dst = sb + tile * ATILE_B + row * AROWB + cc * 16;      \
        const uint16_t* srcp = (tile ? g_ql : g_qh)                            \
                               + ((bhbase + q0 + row) << 6) + cc * 8;          \
        CP_ASYNC16(dst, srcp);                                                 \
    }                                                                          \
    CP_COMMIT;                                                                 \
} while (0)

#define A_ISSUE_KV(kt, s) do {                                                 \
    const int _k0 = (kt) * 64;                                                 \
    const uint32_t _stb = sb + 2 * ATILE_B + (uint32_t)(s) * A_STAGE;          \
    _Pragma("unroll")                                                          \
    for (int t = 0; t < 16; t++) {                                             \
        const int tile = t >> 2;                                               \
        const int idx2 = tid + (t & 3) * 128;                                  \
        const int row = idx2 >> 3, cc = idx2 & 7;                              \
        const uint32_t dst = _stb + tile * ATILE_B + row * AROWB + cc * 16;    \
        const uint16_t* srcp;                                                  \
        if (tile == 0)      srcp = g_kh + ((bhbase + _k0 + row) << 6) + cc * 8;\
        else if (tile == 1) srcp = g_kl + ((bhbase + _k0 + row) << 6) + cc * 8;\
        else if (tile == 2) srcp = g_vh + ((bhbase + _k0 + row) << 6) + cc * 8;\
        else                srcp = g_vl + ((bhbase + _k0 + row) << 6) + cc * 8;\
        CP_ASYNC16(dst, srcp);                                                 \
    }                                                                          \
    CP_COMMIT;                                                                 \
} while (0)

    // prologue: Q + first K/V stage in flight
    A_ISSUE_Q;
    A_ISSUE_KV(0, 0);
    CP_WAIT1;            // Q arrived
    __syncthreads();

    // build Q fragments (Q already scaled by 1/8 in projection)
    uint32_t qh[4][4], ql[4][4];
#pragma unroll
    for (int kk = 0; kk < 4; kk++) {
        const uint32_t aoff = (uint32_t)(ar * AROWB + (kk * 16 + ac8) * 2);
        ldsm4(qh[kk], sb + aoff);
        ldsm4(ql[kk], sb + ATILE_B + aoff);
    }

    float o[8][4];
#pragma unroll
    for (int nf = 0; nf < 8; nf++)
#pragma unroll
        for (int e = 0; e < 4; e++) o[nf][e] = 0.f;
    float m0 = -1e30f, m1 = -1e30f, l0 = 0.f, l1 = 0.f;

    const int r0 = lane >> 2;
    const int c0 = (lane & 3) * 2;

    for (int kt = 0; kt <= qi; kt++) {
        CP_WAIT0;          // stage kt&1 data ready
        __syncthreads();   // all warps done with stage (kt+1)&1 from iter kt-1
        if (kt < qi) A_ISSUE_KV(kt + 1, (kt + 1) & 1);

        const uint32_t st = sb + 2 * ATILE_B + (uint32_t)(kt & 1) * A_STAGE;

        // ---- S = Q K^T ----
        float s[8][4];
#pragma unroll
        for (int nf = 0; nf < 8; nf++)
#pragma unroll
            for (int e = 0; e < 4; e++) s[nf][e] = 0.f;

#pragma unroll
        for (int kk = 0; kk < 4; kk++) {
            uint32_t kh[4][4], kl[4][4];
#pragma unroll
            for (int p = 0; p < 4; p++) {
                const uint32_t boff = (uint32_t)((bn + p * 16) * AROWB + (kk * 16 + bc8) * 2);
                ldsm4(kh[p], st + boff);
                ldsm4(kl[p], st + ATILE_B + boff);
            }
#pragma unroll
            for (int p = 0; p < 4; p++) {
                mma_bf16(s[2*p],   qh[kk], &kh[p][0]);
                mma_bf16(s[2*p+1], qh[kk], &kh[p][2]);
                mma_bf16(s[2*p],   ql[kk], &kh[p][0]);
                mma_bf16(s[2*p+1], ql[kk], &kh[p][2]);
                mma_bf16(s[2*p],   qh[kk], &kl[p][0]);
                mma_bf16(s[2*p+1], qh[kk], &kl[p][2]);
            }
        }

        // ---- causal mask (diagonal tile only) ----
        if (kt == qi) {
            const int lr0 = wid * 16 + r0;
            const int lr1 = lr0 + 8;
#pragma unroll
            for (int nf = 0; nf < 8; nf++) {
                const int lc = nf * 8 + c0;
                if (lc     > lr0) s[nf][0] = -1e30f;
                if (lc + 1 > lr0) s[nf][1] = -1e30f;
                if (lc     > lr1) s[nf][2] = -1e30f;
                if (lc + 1 > lr1) s[nf][3] = -1e30f;
            }
        }

        // ---- online softmax ----
        float mx0 = -1e30f, mx1 = -1e30f;
#pragma unroll
        for (int nf = 0; nf < 8; nf++) {
            mx0 = fmaxf(mx0, fmaxf(s[nf][0], s[nf][1]));
            mx1 = fmaxf(mx1, fmaxf(s[nf][2], s[nf][3]));
        }
        mx0 = fmaxf(mx0, __shfl_xor_sync(0xffffffffu, mx0, 1));
        mx0 = fmaxf(mx0, __shfl_xor_sync(0xffffffffu, mx0, 2));
        mx1 = fmaxf(mx1, __shfl_xor_sync(0xffffffffu, mx1, 1));
        mx1 = fmaxf(mx1, __shfl_xor_sync(0xffffffffu, mx1, 2));

        const float mn0 = fmaxf(m0, mx0);
        const float mn1 = fmaxf(m1, mx1);
        const float fac0 = __expf(m0 - mn0);
        const float fac1 = __expf(m1 - mn1);
        m0 = mn0; m1 = mn1;

        float rs0 = 0.f, rs1 = 0.f;
#pragma unroll
        for (int nf = 0; nf < 8; nf++) {
            s[nf][0] = __expf(s[nf][0] - mn0);
            s[nf][1] = __expf(s[nf][1] - mn0);
            s[nf][2] = __expf(s[nf][2] - mn1);
            s[nf][3] = __expf(s[nf][3] - mn1);
            rs0 += s[nf][0] + s[nf][1];
            rs1 += s[nf][2] + s[nf][3];
        }
        rs0 += __shfl_xor_sync(0xffffffffu, rs0, 1);
        rs0 += __shfl_xor_sync(0xffffffffu, rs0, 2);
        rs1 += __shfl_xor_sync(0xffffffffu, rs1, 1);
        rs1 += __shfl_xor_sync(0xffffffffu, rs1, 2);
        l0 = l0 * fac0 + rs0;
        l1 = l1 * fac1 + rs1;

#pragma unroll
        for (int nf = 0; nf < 8; nf++) {
            o[nf][0] *= fac0; o[nf][1] *= fac0;
            o[nf][2] *= fac1; o[nf][3] *= fac1;
        }

        // ---- O += P V ----
#pragma unroll
        for (int kp = 0; kp < 4; kp++) {
            uint32_t pa_h[4], pa_l[4];
            split2(s[2*kp][0],   s[2*kp][1],   pa_h[0], pa_l[0]);
            split2(s[2*kp][2],   s[2*kp][3],   pa_h[1], pa_l[1]);
            split2(s[2*kp+1][0], s[2*kp+1][1], pa_h[2], pa_l[2]);
            split2(s[2*kp+1][2], s[2*kp+1][3], pa_h[3], pa_l[3]);
#pragma unroll
            for (int gg = 0; gg < 4; gg++) {
                uint32_t vh[4], vl[4];
                const uint32_t voff = (uint32_t)((kp * 16 + vrow) * AROWB + (gg * 16 + vc8) * 2);
                ldsm4t(vh, st + 2 * ATILE_B + voff);
                ldsm4t(vl, st + 3 * ATILE_B + voff);
                mma_bf16(o[2*gg],   pa_h, &vh[0]);
                mma_bf16(o[2*gg+1], pa_h, &vh[2]);
                mma_bf16(o[2*gg],   pa_l, &vh[0]);
                mma_bf16(o[2*gg+1], pa_l, &vh[2]);
                mma_bf16(o[2*gg],   pa_h, &vl[0]);
                mma_bf16(o[2*gg+1], pa_h, &vl[2]);
            }
        }
    }

    // ---- epilogue: y hi/lo bf16, y[b][t][h*64+d] ----
    const int b = bh >> 4, h = bh & 15;
    const float inv0 = 1.f / l0;
    const float inv1 = 1.f / l1;
    const int rg0 = q0 + wid * 16 + r0;
    const int rg1 = rg0 + 8;
#pragma unroll
    for (int nf = 0; nf < 8; nf++) {
        const int col = h * 64 + nf * 8 + c0;
        uint32_t hp, lp;
        split2(o[nf][0] * inv0, o[nf][1] * inv0, hp, lp);
        *(uint32_t*)(g_yh + (size_t)(b * TT + rg0) * CC + col) = hp;
        *(uint32_t*)(g_yl + (size_t)(b * TT + rg0) * CC + col) = lp;
        split2(o[nf][2] * inv1, o[nf][3] * inv1, hp, lp);
        *(uint32_t*)(g_yh + (size_t)(b * TT + rg1) * CC + col) = hp;
        *(uint32_t*)(g_yl + (size_t)(b * TT + rg1) * CC + col) = lp;
    }
#undef A_ISSUE_Q
#undef A_ISSUE_KV
}

// ---------------------------------------------------------------------------
extern "C" void kernel_launch(void* const* d_in, const int* in_sizes, int n_in,
                              void* d_out, int out_size)
{
    const float* x  = (const float*)d_in[0];
    const float* Wq = (const float*)d_in[1];
    const float* bq = (const float*)d_in[2];
    const float* Wk = (const float*)d_in[3];
    const float* bk = (const float*)d_in[4];
    const float* Wv = (const float*)d_in[5];
    const float* bv = (const float*)d_in[6];
    const float* Wp = (const float*)d_in[7];
    const float* bp = (const float*)d_in[8];
    float* out = (float*)d_out;

    cudaFuncSetAttribute(mma_linear, cudaFuncAttributeMaxDynamicSharedMemorySize, G_SMEM);
    cudaFuncSetAttribute(attn_kernel, cudaFuncAttributeMaxDynamicSharedMemorySize, A_SMEM);

    // pre-split
    const int n4x = (int)(NELEM / 4);
    const int n4w = CC * CC / 4;
    split_kernel<<<n4x / 256, 256>>>(x,  0, n4x);
    split_kernel<<<n4w / 256, 256>>>(Wq, 1, n4w);
    split_kernel<<<n4w / 256, 256>>>(Wk, 2, n4w);
    split_kernel<<<n4w / 256, 256>>>(Wv, 3, n4w);
    split_kernel<<<n4w / 256, 256>>>(Wp, 4, n4w);

    dim3 gb(256);
    dim3 gg(NTOK / 128, CC / 128);  // 64 x 8

    mma_linear<<<gg, gb, G_SMEM>>>(0, 0, bq, nullptr, 0);
    mma_linear<<<gg, gb, G_SMEM>>>(0, 1, bk, nullptr, 1);
    mma_linear<<<gg, gb, G_SMEM>>>(0, 2, bv, nullptr, 2);

    attn_kernel<<<dim3(TT / 64, BB * HH), 128, A_SMEM>>>();

    mma_linear<<<gg, gb, G_SMEM>>>(1, 3, bp, out, 3);
}